// round 9
// baseline (speedup 1.0000x reference)
#include <cuda_runtime.h>
#include <cuda_fp16.h>
#include <cstdint>

// ---------------------------------------------------------------------------
// QuanvolutionHybrid — single persistent kernel, 444 blocks (3/SM guaranteed:
// regs<=80 via launch_bounds, 40.5KB static smem -> 121.5KB/SM <= 228KB).
// Closed-form circuit (Heisenberg):
//   Z0 = cos(t4)cos(t0+p0) - sin(t4)sin(t0+p0)sin(p1)
//   Z1 = cos(t0+p0) cos(t1) cos(p1)
//   Z2 = Z1 * cos(p2)
//   Z3 = cos(t3) cos(p2) cos(p3)      (qw[2] provably unused)
// 12 images/block; t1/t2 stay in SMEM across phases; f in global fp16.
// Conv reads are LDS.128 (uniform lane path); f32x2 FMAs throughout.
// ---------------------------------------------------------------------------

#define MAXB 4096
#define E    784
#define NBIN 32
#define FST  20               // tile row stride (floats), 16B-aligned rows
#define FIMG (4 * 16 * FST)   // 1280 floats per image tile
#define NBLK 444
#define IPB  12

typedef unsigned long long u64;

__device__ __half f_h [MAXB * E];
__device__ float stats1_g[NBIN * 8];
__device__ float stats2_g[NBIN * 8];
__device__ unsigned sync_ctr;

__device__ __forceinline__ u64 fma2(u64 a, u64 b, u64 c) {
    u64 d;
    asm("fma.rn.f32x2 %0, %1, %2, %3;" : "=l"(d) : "l"(a), "l"(b), "l"(c));
    return d;
}
__device__ __forceinline__ u64 add2(u64 a, u64 b) {
    u64 d;
    asm("add.rn.f32x2 %0, %1, %2;" : "=l"(d) : "l"(a), "l"(b));
    return d;
}
__device__ __forceinline__ u64 pack2(float lo, float hi) {
    u64 d;
    asm("mov.b64 %0, {%1, %2};" : "=l"(d) : "f"(lo), "f"(hi));
    return d;
}
__device__ __forceinline__ float2 unpack2(u64 v) {
    float lo, hi;
    asm("mov.b64 {%0, %1}, %2;" : "=f"(lo), "=f"(hi) : "l"(v));
    return make_float2(lo, hi);
}

union HPack { uint2 u; __half2 h[2]; };

__global__ void k_init() {
    int t = threadIdx.x;
    if (t == 0) sync_ctr = 0u;
    if (t < NBIN * 8)            stats1_g[t] = 0.f;
    else if (t < 2 * NBIN * 8)   stats2_g[t - NBIN * 8] = 0.f;
}

__device__ __forceinline__ void grid_sync(unsigned target) {
    __syncthreads();
    if (threadIdx.x == 0) {
        __threadfence();
        atomicAdd(&sync_ctr, 1u);
        while (*((volatile unsigned*)&sync_ctr) < target) __nanosleep(64);
        __threadfence();
    }
    __syncthreads();
}

// wt2: duplicated weight pairs; u64 index i=(ic*3+kh)*12+kw*4+oc holds (w,w).
__device__ __forceinline__ void stage_weights(const float* __restrict__ w,
                                              float* wt2, int t) {
    if (t < 144) {
        int oc = t & 3, rest = t >> 2;
        int kw = rest % 3, kh = (rest / 3) % 3, ic = rest / 9;
        float v = w[((oc * 4 + ic) * 3 + kh) * 3 + kw];
        wt2[2 * t] = v;
        wt2[2 * t + 1] = v;
    }
}

// Warp computes 2 output channels (oc=half*2,half*2+1) of the 3x3 conv.
// Lane<28: row=lane>>1, seg=lane&1; seg0 -> px 0..7, seg1 -> px 8..13
// (4th pixel-pair of seg1 is computed and discarded -> uniform path).
// Per (ic,kh): 3x LDS.128.  Results -> smem floats -> t_s halves; stats
// reduced in-warp and atomically binned.  Contains __syncthreads.
__device__ __forceinline__ void warp_conv(
    float* myfz, const float* __restrict__ wt2,
    uint2* __restrict__ t_img, float* __restrict__ stats,
    int b, int lane, int half, bool act)
{
    int row = lane >> 1, seg = lane & 1;
    u64 acc[2][4];
    #pragma unroll
    for (int o = 0; o < 2; o++)
        #pragma unroll
        for (int p = 0; p < 4; p++) acc[o][p] = 0ull;

    if (act && lane < 28) {
        const ulonglong2* wp2 = reinterpret_cast<const ulonglong2*>(wt2);
        #pragma unroll
        for (int ic = 0; ic < 4; ic++) {
            #pragma unroll
            for (int kh = 0; kh < 3; kh++) {
                const float4* vp = reinterpret_cast<const float4*>(
                    myfz + (ic * 16 + row + kh) * FST + seg * 8);
                float4 A0 = vp[0], A1 = vp[1], A2 = vp[2];
                float a[12] = {A0.x, A0.y, A0.z, A0.w,
                               A1.x, A1.y, A1.z, A1.w,
                               A2.x, A2.y, A2.z, A2.w};
                u64 P[9];
                #pragma unroll
                for (int q = 0; q < 9; q++) P[q] = pack2(a[q], a[q + 1]);
                int wbase = (ic * 3 + kh) * 6 + half;
                #pragma unroll
                for (int kw = 0; kw < 3; kw++) {
                    ulonglong2 wv = wp2[wbase + kw * 2];
                    acc[0][0] = fma2(P[kw],     wv.x, acc[0][0]);
                    acc[0][1] = fma2(P[2 + kw], wv.x, acc[0][1]);
                    acc[0][2] = fma2(P[4 + kw], wv.x, acc[0][2]);
                    acc[0][3] = fma2(P[6 + kw], wv.x, acc[0][3]);
                    acc[1][0] = fma2(P[kw],     wv.y, acc[1][0]);
                    acc[1][1] = fma2(P[2 + kw], wv.y, acc[1][1]);
                    acc[1][2] = fma2(P[4 + kw], wv.y, acc[1][2]);
                    acc[1][3] = fma2(P[6 + kw], wv.y, acc[1][3]);
                }
            }
        }
    }
    __syncthreads();                    // all tile reads complete block-wide

    float s[4] = {0.f, 0.f, 0.f, 0.f};
    if (act && lane < 28) {
        #pragma unroll
        for (int o = 0; o < 2; o++) {
            int oc = half * 2 + o;
            float* op = myfz + oc * 196 + row * 14 + seg * 8;
            #pragma unroll
            for (int p = 0; p < 3; p++)
                *reinterpret_cast<float2*>(op + 2 * p) = unpack2(acc[o][p]);
            if (seg == 0)
                *reinterpret_cast<float2*>(op + 6) = unpack2(acc[o][3]);
            u64 sum2 = add2(add2(acc[o][0], acc[o][1]), acc[o][2]);
            u64 sq2  = fma2(acc[o][0], acc[o][0], 0ull);
            sq2      = fma2(acc[o][1], acc[o][1], sq2);
            sq2      = fma2(acc[o][2], acc[o][2], sq2);
            if (seg == 0) {
                sum2 = add2(sum2, acc[o][3]);
                sq2  = fma2(acc[o][3], acc[o][3], sq2);
            }
            float2 us = unpack2(sum2), uq = unpack2(sq2);
            s[o]     = us.x + us.y;
            s[2 + o] = uq.x + uq.y;
        }
    }
    __syncwarp();
    if (act) {
        const float4* ob4 = reinterpret_cast<const float4*>(myfz);
        #pragma unroll
        for (int it = 0; it < 4; it++) {
            int j = it * 32 + lane;
            if (j < 98) {
                int i = half * 98 + j;
                float4 v = ob4[i];
                HPack pk;
                pk.h[0] = __floats2half2_rn(v.x, v.y);
                pk.h[1] = __floats2half2_rn(v.z, v.w);
                t_img[i] = pk.u;
            }
        }
    }
    #pragma unroll
    for (int off = 16; off; off >>= 1)
        #pragma unroll
        for (int c = 0; c < 4; c++)
            s[c] += __shfl_down_sync(0xffffffffu, s[c], off);
    if (act && lane == 0) {
        int base = (b & (NBIN - 1)) * 8 + half * 2;
        atomicAdd(&stats[base],     s[0]);
        atomicAdd(&stats[base + 1], s[1]);
        atomicAdd(&stats[base + 4], s[2]);
        atomicAdd(&stats[base + 5], s[3]);
    }
}

__device__ __forceinline__ void bn_prologue(
    const float* __restrict__ stats, const float* __restrict__ gamma,
    const float* __restrict__ beta, float* sums8, float* sc, float* bi,
    int t, float Ninv)
{
    if (t < 8) {
        float s = 0.f;
        #pragma unroll
        for (int bin = 0; bin < NBIN; bin++) s += stats[bin * 8 + t];
        sums8[t] = s;
    }
    __syncthreads();
    if (t < 4) {
        float mean = sums8[t] * Ninv;
        float var  = sums8[4 + t] * Ninv - mean * mean;
        float s    = gamma[t] * rsqrtf(var + 1e-5f);
        sc[t] = s;
        bi[t] = beta[t] - mean * s;
    }
    __syncthreads();
}

__global__ void __launch_bounds__(256, 3) k_fused(
    const float* __restrict__ x, const float* __restrict__ qw,
    const float* __restrict__ w1, const float* __restrict__ g1,
    const float* __restrict__ be1, const float* __restrict__ w2,
    const float* __restrict__ g2, const float* __restrict__ be2,
    const float* __restrict__ fcw, const float* __restrict__ fcb,
    float* __restrict__ out, int B)
{
    __shared__ __align__(16) float  tile[4 * FIMG];      // 20480 B (4 images)
    __shared__ __align__(16) __half t_s[IPB * E];        // 18816 B
    __shared__ __align__(16) float  wt2[288];            //  1152 B
    __shared__ float sums8[8], sc[4], bi[4];

    int t = threadIdx.x, warp = t >> 5, lane = t & 31;
    int m = warp >> 1, half = warp & 1;     // tile slot, oc-half
    int b0 = blockIdx.x * IPB;
    float Ninv = 1.f / ((float)B * 196.f);

    // ======================= PHASE 1: quantum + conv1 =======================
    stage_weights(w1, wt2, t);

    float q0 = qw[0], q1 = qw[1], q3 = qw[3], q4 = qw[4];
    float ct1 = __cosf(q1), ct3 = __cosf(q3);
    float st4, ct4; __sincosf(q4, &st4, &ct4);

    #pragma unroll
    for (int g = 0; g < IPB / 4; g++) {
        int idx = g * 4 + m;
        int b = b0 + idx;
        bool act = (b < B);

        __syncthreads();                 // previous iteration's tile dead
        float4* tz = reinterpret_cast<float4*>(tile);
        #pragma unroll
        for (int k = 0; k < 5; k++) tz[t + 256 * k] = make_float4(0.f, 0.f, 0.f, 0.f);
        __syncthreads();

        float* myfz = tile + m * FIMG;
        if (act) {
            const float* xb = x + (size_t)b * E;
            uint2* fdst = reinterpret_cast<uint2*>(f_h + (size_t)b * E);
            #pragma unroll
            for (int it = 0; it < 4; it++) {
                int j = it * 32 + lane;
                if (j < 98) {
                    int p = half * 98 + j;
                    int i = p / 14, jj = p % 14;
                    float2 r0 = *reinterpret_cast<const float2*>(xb + i * 56 + jj * 2);
                    float2 r1 = *reinterpret_cast<const float2*>(xb + i * 56 + 28 + jj * 2);
                    float sa, ca;   __sincosf(q0 + r0.x, &sa, &ca);
                    float sp1, cp1; __sincosf(r0.y, &sp1, &cp1);
                    float cp2 = __cosf(r1.x), cp3 = __cosf(r1.y);

                    float m0 = ct4 * ca - st4 * sa * sp1;
                    float m1 = ca * ct1 * cp1;
                    float m2 = m1 * cp2;
                    float m3 = ct3 * cp2 * cp3;

                    HPack pk;
                    pk.h[0] = __floats2half2_rn(m0, m1);
                    pk.h[1] = __floats2half2_rn(m2, m3);
                    fdst[p] = pk.u;

                    float mv[4] = {m0, m1, m2, m3};
                    #pragma unroll
                    for (int q = 0; q < 4; q++) {
                        int e = p * 4 + q, c = e / 196, rr = e % 196;
                        myfz[(c * 16 + rr / 14 + 1) * FST + rr % 14 + 1] = mv[q];
                    }
                }
            }
        }
        __syncthreads();
        warp_conv(myfz, wt2, reinterpret_cast<uint2*>(t_s + idx * E),
                  stats1_g, b, lane, half, act);
    }

    grid_sync(NBLK);                     // stats1 complete everywhere

    // ======================= PHASE 2: bn1+relu + conv2 ======================
    stage_weights(w2, wt2, t);
    bn_prologue(stats1_g, g1, be1, sums8, sc, bi, t, Ninv);

    #pragma unroll
    for (int g = 0; g < IPB / 4; g++) {
        int idx = g * 4 + m;
        int b = b0 + idx;
        bool act = (b < B);

        __syncthreads();
        float4* tz = reinterpret_cast<float4*>(tile);
        #pragma unroll
        for (int k = 0; k < 5; k++) tz[t + 256 * k] = make_float4(0.f, 0.f, 0.f, 0.f);
        __syncthreads();

        float* myfz = tile + m * FIMG;
        if (act) {
            const uint2* src = reinterpret_cast<const uint2*>(t_s + idx * E);
            #pragma unroll
            for (int it = 0; it < 4; it++) {
                int j = it * 32 + lane;
                if (j < 98) {
                    int e4 = half * 98 + j;
                    HPack pk; pk.u = src[e4];
                    float2 lo = __half22float2(pk.h[0]);
                    float2 hi = __half22float2(pk.h[1]);
                    int c = e4 / 49;
                    float s = sc[c], o = bi[c];
                    float vv[4] = { fmaxf(lo.x*s+o, 0.f), fmaxf(lo.y*s+o, 0.f),
                                    fmaxf(hi.x*s+o, 0.f), fmaxf(hi.y*s+o, 0.f) };
                    int rr = (e4 * 4) % 196;
                    #pragma unroll
                    for (int q = 0; q < 4; q++) {
                        int rq = rr + q;
                        myfz[(c * 16 + rq / 14 + 1) * FST + rq % 14 + 1] = vv[q];
                    }
                }
            }
        }
        __syncthreads();
        warp_conv(myfz, wt2, reinterpret_cast<uint2*>(t_s + idx * E),
                  stats2_g, b, lane, half, act);
    }

    grid_sync(2 * NBLK);                 // stats2 complete everywhere

    // ============ PHASE 3: bn2 + residual + relu + fc + softmax =============
    bn_prologue(stats2_g, g2, be2, sums8, sc, bi, t, Ninv);

    for (int i = warp; i < IPB; i += 8) {
        int b = b0 + i;
        if (b >= B) break;

        const uint2* tA = reinterpret_cast<const uint2*>(t_s + i * E);
        const uint2* fA = reinterpret_cast<const uint2*>(f_h + (size_t)b * E);
        const float4* fw4 = reinterpret_cast<const float4*>(fcw);

        u64 acc[10];
        #pragma unroll
        for (int k = 0; k < 10; k++) acc[k] = 0ull;

        #pragma unroll
        for (int it = 0; it < 7; it++) {
            int i4 = it * 32 + lane;
            if (i4 < 196) {
                int c = i4 / 49;
                float s = sc[c], o = bi[c];
                HPack ta; ta.u = tA[i4];
                HPack fa; fa.u = fA[i4];
                float2 tl = __half22float2(ta.h[0]), th = __half22float2(ta.h[1]);
                float2 fl = __half22float2(fa.h[0]), fh = __half22float2(fa.h[1]);
                u64 A1 = pack2(fmaxf(tl.x*s+o+fl.x, 0.f), fmaxf(tl.y*s+o+fl.y, 0.f));
                u64 A2 = pack2(fmaxf(th.x*s+o+fh.x, 0.f), fmaxf(th.y*s+o+fh.y, 0.f));
                #pragma unroll
                for (int k = 0; k < 10; k++) {
                    float4 wv = __ldg(&fw4[k * 196 + i4]);
                    acc[k] = fma2(A1, pack2(wv.x, wv.y), acc[k]);
                    acc[k] = fma2(A2, pack2(wv.z, wv.w), acc[k]);
                }
            }
        }
        float sA[10];
        #pragma unroll
        for (int k = 0; k < 10; k++) {
            float2 u = unpack2(acc[k]);
            sA[k] = u.x + u.y;
        }
        #pragma unroll
        for (int off = 16; off; off >>= 1)
            #pragma unroll
            for (int k = 0; k < 10; k++)
                sA[k] += __shfl_down_sync(0xffffffffu, sA[k], off);

        if (lane == 0) {
            float lg[10], mx = -1e30f;
            #pragma unroll
            for (int k = 0; k < 10; k++) {
                lg[k] = sA[k] + fcb[k];
                mx = fmaxf(mx, lg[k]);
            }
            float se = 0.f;
            #pragma unroll
            for (int k = 0; k < 10; k++) se += expf(lg[k] - mx);
            float lse = mx + logf(se);
            #pragma unroll
            for (int k = 0; k < 10; k++)
                out[(size_t)b * 10 + k] = lg[k] - lse;
        }
    }
}

extern "C" void kernel_launch(void* const* d_in, const int* in_sizes, int n_in,
                              void* d_out, int out_size)
{
    const float* x   = (const float*)d_in[0];
    const float* qw  = (const float*)d_in[1];
    const float* w1  = (const float*)d_in[2];
    const float* g1  = (const float*)d_in[3];
    const float* be1 = (const float*)d_in[4];
    const float* w2  = (const float*)d_in[5];
    const float* g2  = (const float*)d_in[6];
    const float* be2 = (const float*)d_in[7];
    const float* fcw = (const float*)d_in[8];
    const float* fcb = (const float*)d_in[9];
    float* out = (float*)d_out;

    int B = in_sizes[0] / E;
    if (B > MAXB) B = MAXB;

    k_init<<<1, 512>>>();
    k_fused<<<NBLK, 256>>>(x, qw, w1, g1, be1, w2, g2, be2, fcw, fcb, out, B);
}

// round 10
// speedup vs baseline: 1.2791x; 1.2791x over previous
#include <cuda_runtime.h>
#include <cuda_fp16.h>
#include <cstdint>

// ---------------------------------------------------------------------------
// QuanvolutionHybrid: closed-form quantum features + conv/bn/residual + fc.
//   Z0 = cos(t4)cos(t0+p0) - sin(t4)sin(t0+p0)sin(p1)
//   Z1 = cos(t0+p0) cos(t1) cos(p1)
//   Z2 = Z1 * cos(p2)
//   Z3 = cos(t3) cos(p2) cos(p3)      (qw[2] provably unused)
// fp16 intermediates; global loads hoisted ahead of all prologue work.
// ---------------------------------------------------------------------------

#define MAXB 4096
#define E    784
#define NBIN 32
#define FST  17
#define FIMG (4 * 16 * FST)   // 1088 floats per image tile

typedef unsigned long long u64;

__device__ __half f_h [MAXB * E];
__device__ __half t1_h[MAXB * E];
__device__ __half t2_h[MAXB * E];
__device__ float stats1_g[NBIN * 8];
__device__ float stats2_g[NBIN * 8];

__device__ __forceinline__ u64 fma2(u64 a, u64 b, u64 c) {
    u64 d;
    asm("fma.rn.f32x2 %0, %1, %2, %3;" : "=l"(d) : "l"(a), "l"(b), "l"(c));
    return d;
}
__device__ __forceinline__ u64 pack2(float lo, float hi) {
    u64 d;
    asm("mov.b64 %0, {%1, %2};" : "=l"(d) : "f"(lo), "f"(hi));
    return d;
}
__device__ __forceinline__ float2 unpack2(u64 v) {
    float lo, hi;
    asm("mov.b64 {%0, %1}, %2;" : "=f"(lo), "=f"(hi) : "l"(v));
    return make_float2(lo, hi);
}

union HPack { uint2 u; __half2 h[2]; };

__global__ void k_init() {
    int t = threadIdx.x;
    if (t < NBIN * 8)            stats1_g[t] = 0.f;
    else if (t < 2 * NBIN * 8)   stats2_g[t - NBIN * 8] = 0.f;
}

// wt2: duplicated pairs; u64 index i=(ic*3+kh)*12+kw*4+oc holds (w,w).
__device__ __forceinline__ void stage_weights(const float* __restrict__ w,
                                              float* wt2, int t, int nthr) {
    for (int i = t; i < 144; i += nthr) {
        int oc = i & 3, rest = i >> 2;
        int kw = rest % 3, kh = (rest / 3) % 3, ic = rest / 9;
        float v = w[((oc * 4 + ic) * 3 + kh) * 3 + kw];
        wt2[2 * i] = v;
        wt2[2 * i + 1] = v;
    }
}

// Warp computes 2 output channels (oc=half*2,half*2+1) of the 3x3 conv on one
// image tile. Lane<28: half-row (7 px). Results staged to smem (tile dead
// after block sync) then copied out coalesced; stats via warp reduce+atomics.
// Contains __syncthreads: call from ALL threads of the block.
__device__ __forceinline__ void warp_conv(
    float* myfz, const float* __restrict__ wt2,
    uint2* __restrict__ dst, float* __restrict__ stats,
    int b, int lane, int half, bool act)
{
    u64 acc[2][4];
    #pragma unroll
    for (int o = 0; o < 2; o++)
        #pragma unroll
        for (int p = 0; p < 4; p++) acc[o][p] = 0ull;

    if (act && lane < 28) {
        int row = lane >> 1, w0 = (lane & 1) * 7;
        const ulonglong2* wp2 = reinterpret_cast<const ulonglong2*>(wt2);
        #pragma unroll
        for (int ic = 0; ic < 4; ic++) {
            #pragma unroll
            for (int kh = 0; kh < 3; kh++) {
                const float* rp = myfz + (ic * 16 + row + kh) * FST + w0;
                float a[10];
                #pragma unroll
                for (int q = 0; q < 10; q++) a[q] = rp[q];
                u64 P[9];
                #pragma unroll
                for (int q = 0; q < 9; q++) P[q] = pack2(a[q], a[q + 1]);
                int wbase = (ic * 3 + kh) * 6 + half;
                #pragma unroll
                for (int kw = 0; kw < 3; kw++) {
                    ulonglong2 wv = wp2[wbase + kw * 2];
                    acc[0][0] = fma2(P[kw],     wv.x, acc[0][0]);
                    acc[0][1] = fma2(P[2 + kw], wv.x, acc[0][1]);
                    acc[0][2] = fma2(P[4 + kw], wv.x, acc[0][2]);
                    acc[0][3] = fma2(P[6 + kw], wv.x, acc[0][3]);
                    acc[1][0] = fma2(P[kw],     wv.y, acc[1][0]);
                    acc[1][1] = fma2(P[2 + kw], wv.y, acc[1][1]);
                    acc[1][2] = fma2(P[4 + kw], wv.y, acc[1][2]);
                    acc[1][3] = fma2(P[6 + kw], wv.y, acc[1][3]);
                }
            }
        }
    }
    __syncthreads();                 // tile reads complete block-wide

    float s[4] = {0.f, 0.f, 0.f, 0.f};
    if (act && lane < 28) {
        #pragma unroll
        for (int o = 0; o < 2; o++) {
            int oc = half * 2 + o;
            float2 u0 = unpack2(acc[o][0]);
            float2 u1 = unpack2(acc[o][1]);
            float2 u2 = unpack2(acc[o][2]);
            float2 u3 = unpack2(acc[o][3]);   // .y garbage (px 7)
            float v[7] = {u0.x, u0.y, u1.x, u1.y, u2.x, u2.y, u3.x};
            float* op = myfz + oc * 196 + lane * 7;
            #pragma unroll
            for (int j = 0; j < 7; j++) {
                op[j] = v[j];
                s[o]     += v[j];
                s[2 + o] += v[j] * v[j];
            }
        }
    }
    __syncwarp();
    if (act) {
        const float4* ob4 = reinterpret_cast<const float4*>(myfz);
        #pragma unroll
        for (int it = 0; it < 4; it++) {
            int j = it * 32 + lane;
            if (j < 98) {
                int i = half * 98 + j;
                float4 v = ob4[i];
                HPack pk;
                pk.h[0] = __floats2half2_rn(v.x, v.y);
                pk.h[1] = __floats2half2_rn(v.z, v.w);
                dst[i] = pk.u;
            }
        }
    }
    #pragma unroll
    for (int off = 16; off; off >>= 1)
        #pragma unroll
        for (int c = 0; c < 4; c++)
            s[c] += __shfl_down_sync(0xffffffffu, s[c], off);
    if (act && lane == 0) {
        int base = (b & (NBIN - 1)) * 8 + half * 2;
        atomicAdd(&stats[base],     s[0]);
        atomicAdd(&stats[base + 1], s[1]);
        atomicAdd(&stats[base + 4], s[2]);
        atomicAdd(&stats[base + 5], s[3]);
    }
}

__device__ __forceinline__ void bn_prologue(
    const float* __restrict__ stats, const float* __restrict__ gamma,
    const float* __restrict__ beta, float* sums8, float* sc, float* bi,
    int t, float Ninv)
{
    if (t < 8) {
        float s = 0.f;
        #pragma unroll
        for (int bin = 0; bin < NBIN; bin++) s += stats[bin * 8 + t];
        sums8[t] = s;
    }
    __syncthreads();
    if (t < 4) {
        float mean = sums8[t] * Ninv;
        float var  = sums8[4 + t] * Ninv - mean * mean;
        float s    = gamma[t] * rsqrtf(var + 1e-5f);
        sc[t] = s;
        bi[t] = beta[t] - mean * s;
    }
    __syncthreads();
}

// K1: quantum + conv1 + stats1.  2 warps/image, 2 images per 128-thr block.
// x loads hoisted to the very top (overlap tile zero + weight staging).
__global__ void __launch_bounds__(128) k_quanv_conv1(
    const float* __restrict__ x, const float* __restrict__ qw,
    const float* __restrict__ w1, int B)
{
    __shared__ __align__(16) float fz[2 * FIMG];
    __shared__ __align__(16) float wt2[288];
    int t = threadIdx.x, warp = t >> 5, lane = t & 31;
    int m = warp >> 1, half = warp & 1;
    int b = blockIdx.x * 2 + m;
    bool act = (b < B);

    // --- hoisted x loads (4 px per lane max) ---
    float2 xr0[4], xr1[4];
    const float* xb = x + (size_t)b * E;
    #pragma unroll
    for (int it = 0; it < 4; it++) {
        int j = it * 32 + lane;
        if (act && j < 98) {
            int p = half * 98 + j;
            int i = p / 14, jj = p % 14;
            xr0[it] = *reinterpret_cast<const float2*>(xb + i * 56 + jj * 2);
            xr1[it] = *reinterpret_cast<const float2*>(xb + i * 56 + 28 + jj * 2);
        }
    }

    stage_weights(w1, wt2, t, 128);
    float4* tz = reinterpret_cast<float4*>(fz);
    for (int i = t; i < 2 * FIMG / 4; i += 128)
        tz[i] = make_float4(0.f, 0.f, 0.f, 0.f);
    __syncthreads();

    float* myfz = fz + m * FIMG;
    if (act) {
        float q0 = qw[0], q1 = qw[1], q3 = qw[3], q4 = qw[4];
        float ct1 = __cosf(q1), ct3 = __cosf(q3);
        float st4, ct4; __sincosf(q4, &st4, &ct4);
        uint2* fdst = reinterpret_cast<uint2*>(f_h + (size_t)b * E);
        #pragma unroll
        for (int it = 0; it < 4; it++) {
            int j = it * 32 + lane;
            if (j < 98) {
                int p = half * 98 + j;
                float sa, ca;   __sincosf(q0 + xr0[it].x, &sa, &ca);
                float sp1, cp1; __sincosf(xr0[it].y, &sp1, &cp1);
                float cp2 = __cosf(xr1[it].x), cp3 = __cosf(xr1[it].y);

                float m0 = ct4 * ca - st4 * sa * sp1;
                float m1 = ca * ct1 * cp1;
                float m2 = m1 * cp2;
                float m3 = ct3 * cp2 * cp3;

                HPack pk;
                pk.h[0] = __floats2half2_rn(m0, m1);
                pk.h[1] = __floats2half2_rn(m2, m3);
                fdst[p] = pk.u;

                float mv[4] = {m0, m1, m2, m3};
                #pragma unroll
                for (int q = 0; q < 4; q++) {
                    int e = p * 4 + q, c = e / 196, rr = e % 196;
                    myfz[(c * 16 + rr / 14 + 1) * FST + rr % 14 + 1] = mv[q];
                }
            }
        }
    }
    __syncthreads();
    warp_conv(myfz, wt2, reinterpret_cast<uint2*>(t1_h + (size_t)b * E),
              stats1_g, b, lane, half, act);
}

// K2: bn1+relu + conv2 + stats2.  Same shape; t1 loads hoisted ahead of
// zeroing + bn_prologue.
__global__ void __launch_bounds__(128) k_conv2(
    const float* __restrict__ w2, const float* __restrict__ g1,
    const float* __restrict__ be1, int B)
{
    __shared__ __align__(16) float fz[2 * FIMG];
    __shared__ __align__(16) float wt2[288];
    __shared__ float sums8[8], sc[4], bi[4];
    int t = threadIdx.x, warp = t >> 5, lane = t & 31;
    int m = warp >> 1, half = warp & 1;
    int b = blockIdx.x * 2 + m;
    bool act = (b < B);

    // --- hoisted t1 loads ---
    uint2 tv[4];
    const uint2* src = reinterpret_cast<const uint2*>(t1_h + (size_t)b * E);
    #pragma unroll
    for (int it = 0; it < 4; it++) {
        int j = it * 32 + lane;
        if (act && j < 98) tv[it] = src[half * 98 + j];
    }

    stage_weights(w2, wt2, t, 128);
    float4* tz = reinterpret_cast<float4*>(fz);
    for (int i = t; i < 2 * FIMG / 4; i += 128)
        tz[i] = make_float4(0.f, 0.f, 0.f, 0.f);

    bn_prologue(stats1_g, g1, be1, sums8, sc, bi, t, 1.f / ((float)B * 196.f));

    float* myfz = fz + m * FIMG;
    if (act) {
        #pragma unroll
        for (int it = 0; it < 4; it++) {
            int j = it * 32 + lane;
            if (j < 98) {
                int e4 = half * 98 + j;
                HPack pk; pk.u = tv[it];
                float2 lo = __half22float2(pk.h[0]);
                float2 hi = __half22float2(pk.h[1]);
                int c = e4 / 49;
                float s = sc[c], o = bi[c];
                float vv[4] = { fmaxf(lo.x*s+o, 0.f), fmaxf(lo.y*s+o, 0.f),
                                fmaxf(hi.x*s+o, 0.f), fmaxf(hi.y*s+o, 0.f) };
                int rr = (e4 * 4) % 196;
                #pragma unroll
                for (int q = 0; q < 4; q++) {
                    int rq = rr + q;
                    myfz[(c * 16 + rq / 14 + 1) * FST + rq % 14 + 1] = vv[q];
                }
            }
        }
    }
    __syncthreads();
    warp_conv(myfz, wt2, reinterpret_cast<uint2*>(t2_h + (size_t)b * E),
              stats2_g, b, lane, half, act);
}

// K3: bn2 + residual + relu + fc + log_softmax.  1 image/warp, 4/block.
// t2/f loads hoisted ahead of bn_prologue; fcw via __ldg (L1-resident).
__global__ void __launch_bounds__(128) k_fc(
    const float* __restrict__ g2, const float* __restrict__ be2,
    const float* __restrict__ fcw, const float* __restrict__ fcb,
    float* __restrict__ out, int B)
{
    __shared__ float sums8[8], sc[4], bi[4];
    int t = threadIdx.x, warp = t >> 5, lane = t & 31;
    int b = blockIdx.x * 4 + warp;
    bool act = (b < B);

    // --- hoisted t2/f loads (7 uint2 each) ---
    uint2 tv[7], fv[7];
    const uint2* tA = reinterpret_cast<const uint2*>(t2_h + (size_t)b * E);
    const uint2* fA = reinterpret_cast<const uint2*>(f_h  + (size_t)b * E);
    #pragma unroll
    for (int it = 0; it < 7; it++) {
        int i = it * 32 + lane;
        if (act && i < 196) { tv[it] = tA[i]; fv[it] = fA[i]; }
    }

    bn_prologue(stats2_g, g2, be2, sums8, sc, bi, t, 1.f / ((float)B * 196.f));
    if (!act) return;

    const float4* fw4 = reinterpret_cast<const float4*>(fcw);
    u64 acc[10];
    #pragma unroll
    for (int k = 0; k < 10; k++) acc[k] = 0ull;

    #pragma unroll
    for (int it = 0; it < 7; it++) {
        int i = it * 32 + lane;
        if (i < 196) {
            int c = i / 49;
            float s = sc[c], o = bi[c];
            HPack ta; ta.u = tv[it];
            HPack fa; fa.u = fv[it];
            float2 tl = __half22float2(ta.h[0]), th = __half22float2(ta.h[1]);
            float2 fl = __half22float2(fa.h[0]), fh = __half22float2(fa.h[1]);
            u64 A1 = pack2(fmaxf(tl.x*s+o+fl.x, 0.f), fmaxf(tl.y*s+o+fl.y, 0.f));
            u64 A2 = pack2(fmaxf(th.x*s+o+fh.x, 0.f), fmaxf(th.y*s+o+fh.y, 0.f));
            #pragma unroll
            for (int k = 0; k < 10; k++) {
                float4 wv = __ldg(&fw4[k * 196 + i]);
                acc[k] = fma2(A1, pack2(wv.x, wv.y), acc[k]);
                acc[k] = fma2(A2, pack2(wv.z, wv.w), acc[k]);
            }
        }
    }
    float sA[10];
    #pragma unroll
    for (int k = 0; k < 10; k++) {
        float2 u = unpack2(acc[k]);
        sA[k] = u.x + u.y;
    }
    #pragma unroll
    for (int off = 16; off; off >>= 1)
        #pragma unroll
        for (int k = 0; k < 10; k++)
            sA[k] += __shfl_down_sync(0xffffffffu, sA[k], off);

    if (lane == 0) {
        float lg[10], mx = -1e30f;
        #pragma unroll
        for (int k = 0; k < 10; k++) {
            lg[k] = sA[k] + fcb[k];
            mx = fmaxf(mx, lg[k]);
        }
        float se = 0.f;
        #pragma unroll
        for (int k = 0; k < 10; k++) se += expf(lg[k] - mx);
        float lse = mx + logf(se);
        #pragma unroll
        for (int k = 0; k < 10; k++)
            out[(size_t)b * 10 + k] = lg[k] - lse;
    }
}

extern "C" void kernel_launch(void* const* d_in, const int* in_sizes, int n_in,
                              void* d_out, int out_size)
{
    const float* x   = (const float*)d_in[0];
    const float* qw  = (const float*)d_in[1];
    const float* w1  = (const float*)d_in[2];
    const float* g1  = (const float*)d_in[3];
    const float* be1 = (const float*)d_in[4];
    const float* w2  = (const float*)d_in[5];
    const float* g2  = (const float*)d_in[6];
    const float* be2 = (const float*)d_in[7];
    const float* fcw = (const float*)d_in[8];
    const float* fcb = (const float*)d_in[9];
    float* out = (float*)d_out;

    int B = in_sizes[0] / E;
    if (B > MAXB) B = MAXB;

    k_init<<<1, 512>>>();
    k_quanv_conv1<<<(B + 1) / 2, 128>>>(x, qw, w1, B);
    k_conv2<<<(B + 1) / 2, 128>>>(w2, g1, be1, B);
    k_fc<<<(B + 3) / 4, 128>>>(g2, be2, fcw, fcb, out, B);
}